// round 9
// baseline (speedup 1.0000x reference)
#include <cuda_runtime.h>
#include <cuda_fp16.h>

#define V_N  100000
#define B_N  8
#define FC_N 200000
#define U_N  1024
#define T_N  110000
#define K_N  2
#define EPS_F 1e-5f

// Scratch:
__device__ float2 g_vxy[V_N * B_N];  // transposed verts xy [v][b], 6.4 MB
__device__ float  g_vz [V_N * B_N];  // transposed verts z  [v][b], 3.2 MB
__device__ float  g_vnc[V_N * 24];   // accum vn, [v][c][8 batches], 9.6 MB
__device__ uint2  g_vnh[V_N * B_N];  // normalized vn as half4 [v][b], 6.4 MB

__device__ __forceinline__ void red_add_v4(float* ptr, float a, float b, float c, float d) {
    asm volatile("red.global.add.v4.f32 [%0], {%1, %2, %3, %4};"
                 :: "l"(ptr), "f"(a), "f"(b), "f"(c), "f"(d)
                 : "memory");
}

// Transpose verts -> split xy/z arrays AND zero g_vnc. b fastest => coalesced.
__global__ __launch_bounds__(256) void prep_kernel(const float* __restrict__ verts) {
    int i = blockIdx.x * blockDim.x + threadIdx.x;
    if (i >= V_N * B_N) return;
    int v = i >> 3;
    int b = i & 7;
    const float* p = verts + (size_t)b * (V_N * 3) + v * 3;
    float x = __ldg(p), y = __ldg(p + 1), z = __ldg(p + 2);
    g_vxy[i] = make_float2(x, y);
    g_vz[i]  = z;
    g_vnc[i * 3 + 0] = 0.f;
    g_vnc[i * 3 + 1] = 0.f;
    g_vnc[i * 3 + 2] = 0.f;
}

// One thread per (face, batch-half): computes 4 batches' normals, issues
// 9 red.v4 (3 components x 3 vertices), each covering 4 batches.
__global__ __launch_bounds__(256) void face_pass_kernel(const int* __restrict__ vi)
{
    int tid = blockIdx.x * blockDim.x + threadIdx.x;
    if (tid >= FC_N * 2) return;
    int f  = tid >> 1;
    int bo = (tid & 1) * 4;

    int i0 = __ldg(&vi[f * 3 + 0]);
    int i1 = __ldg(&vi[f * 3 + 1]);
    int i2 = __ldg(&vi[f * 3 + 2]);

    // Load 4 batches of each vertex: 2x float4 (xy pairs) + 1x float4 (z).
    const float4* A01p = reinterpret_cast<const float4*>(&g_vxy[i0 * B_N + bo]);
    float4 A01 = __ldg(A01p), A23 = __ldg(A01p + 1);
    float4 Azv = __ldg(reinterpret_cast<const float4*>(&g_vz[i0 * B_N + bo]));

    const float4* B01p = reinterpret_cast<const float4*>(&g_vxy[i1 * B_N + bo]);
    float4 B01 = __ldg(B01p), B23 = __ldg(B01p + 1);
    float4 Bzv = __ldg(reinterpret_cast<const float4*>(&g_vz[i1 * B_N + bo]));

    const float4* C01p = reinterpret_cast<const float4*>(&g_vxy[i2 * B_N + bo]);
    float4 C01 = __ldg(C01p), C23 = __ldg(C01p + 1);
    float4 Czv = __ldg(reinterpret_cast<const float4*>(&g_vz[i2 * B_N + bo]));

    float Ax[4] = {A01.x, A01.z, A23.x, A23.z};
    float Ay[4] = {A01.y, A01.w, A23.y, A23.w};
    float Az[4] = {Azv.x, Azv.y, Azv.z, Azv.w};
    float Bx[4] = {B01.x, B01.z, B23.x, B23.z};
    float By[4] = {B01.y, B01.w, B23.y, B23.w};
    float Bz[4] = {Bzv.x, Bzv.y, Bzv.z, Bzv.w};
    float Cx[4] = {C01.x, C01.z, C23.x, C23.z};
    float Cy[4] = {C01.y, C01.w, C23.y, C23.w};
    float Cz[4] = {Czv.x, Czv.y, Czv.z, Czv.w};

    float nx[4], ny[4], nz[4];
    #pragma unroll
    for (int l = 0; l < 4; l++) {
        float e1x = Bx[l] - Ax[l], e1y = By[l] - Ay[l], e1z = Bz[l] - Az[l];
        float e2x = Cx[l] - Ax[l], e2y = Cy[l] - Ay[l], e2z = Cz[l] - Az[l];
        float x = e1y * e2z - e1z * e2y;
        float y = e1z * e2x - e1x * e2z;
        float z = e1x * e2y - e1y * e2x;
        float nrm = sqrtf(x * x + y * y + z * z);
        if (nrm >= EPS_F) {
            float inv = 1.f / nrm;
            x *= inv; y *= inv; z *= inv;
        }
        nx[l] = x; ny[l] = y; nz[l] = z;
    }

    #pragma unroll
    for (int s = 0; s < 3; s++) {
        int v = (s == 0) ? i0 : (s == 1) ? i1 : i2;
        float* base = &g_vnc[v * 24 + bo];
        red_add_v4(base +  0, nx[0], nx[1], nx[2], nx[3]);
        red_add_v4(base +  8, ny[0], ny[1], ny[2], ny[3]);
        red_add_v4(base + 16, nz[0], nz[1], nz[2], nz[3]);
    }
}

// Normalize in fp32, emit half4.
__global__ __launch_bounds__(256) void norm_vn_kernel() {
    int i = blockIdx.x * blockDim.x + threadIdx.x;
    if (i >= V_N * B_N) return;
    int v = i >> 3;
    int b = i & 7;
    float x = g_vnc[v * 24 + b];
    float y = g_vnc[v * 24 + 8 + b];
    float z = g_vnc[v * 24 + 16 + b];
    float nrm = sqrtf(x * x + y * y + z * z);
    if (nrm >= EPS_F) {
        float inv = 1.f / nrm;
        x *= inv; y *= inv; z *= inv;
    }
    __half2 xy = __floats2half2_rn(x, y);
    __half2 z0 = __floats2half2_rn(z, 0.f);
    uint2 u;
    *reinterpret_cast<__half2*>(&u.x) = xy;
    *reinterpret_cast<__half2*>(&u.y) = z0;
    g_vnh[i] = u;
}

// Two-stage sample pass (R8 form — frozen), block = 32 vertices, 256 threads.
__global__ __launch_bounds__(256) void sample_pass_kernel(
    const float* __restrict__ bary,
    const float* __restrict__ vt,
    const int*   __restrict__ idximg,
    const int*   __restrict__ v2uv,
    float*       __restrict__ out)
{
    __shared__ float sout[32 * B_N * 3];

    int local = threadIdx.x;
    int lane  = local & 31;

    // ---- stage 1: tap record in registers ----
    int   j0 = 0, j1 = 0, j2 = 0;
    float w0 = 0.f, w1 = 0.f, w2 = 0.f;
    {
        int vloc = local >> 3;
        int k    = (local >> 2) & 1;
        int tap  = local & 3;
        int v    = blockIdx.x * 32 + vloc;

        if (v < V_N) {
            int t = __ldg(&v2uv[v * K_N + k]);
            float2 uv = __ldg(reinterpret_cast<const float2*>(vt) + t);

            float ix = uv.x * (float)U_N - 0.5f;
            float iy = uv.y * (float)U_N - 0.5f;
            float x0f = floorf(ix), y0f = floorf(iy);
            int x0 = (int)x0f, y0 = (int)y0f;
            float wx1 = ix - x0f, wx0 = 1.f - wx1;
            float wy1 = iy - y0f, wy0 = 1.f - wy1;

            int xi = x0 + (tap & 1);
            int yi = y0 + (tap >> 1);
            bool inb = (xi >= 0) & (xi < U_N) & (yi >= 0) & (yi < U_N);
            int xc = min(max(xi, 0), U_N - 1);
            int yc = min(max(yi, 0), U_N - 1);
            int pix = yc * U_N + xc;

            int a0 = __ldg(&idximg[pix * 3 + 0]);
            int a1 = __ldg(&idximg[pix * 3 + 1]);
            int a2 = __ldg(&idximg[pix * 3 + 2]);
            bool valid = inb & (a0 != -1) & (a1 != -1) & (a2 != -1);

            float wt = ((tap & 1) ? wx1 : wx0) * ((tap >> 1) ? wy1 : wy0);
            wt = valid ? wt : 0.f;

            float b0 = __ldg(&bary[pix * 3 + 0]);
            float b1 = __ldg(&bary[pix * 3 + 1]);
            float b2 = __ldg(&bary[pix * 3 + 2]);

            j0 = min(max(a0, 0), V_N - 1);
            j1 = min(max(a1, 0), V_N - 1);
            j2 = min(max(a2, 0), V_N - 1);
            w0 = wt * b0; w1 = wt * b1; w2 = wt * b2;
        }
    }

    // ---- stage 2: (vloc, b); shuffle the 8 records from own subgroup ----
    {
        int b       = local & 7;
        int srcbase = lane & 24;

        float accx = 0.f, accy = 0.f, accz = 0.f;

        #pragma unroll
        for (int e = 0; e < 8; e++) {
            int src = srcbase + e;
            int   sj0 = __shfl_sync(0xffffffffu, j0, src);
            int   sj1 = __shfl_sync(0xffffffffu, j1, src);
            int   sj2 = __shfl_sync(0xffffffffu, j2, src);
            float sw0 = __shfl_sync(0xffffffffu, w0, src);
            float sw1 = __shfl_sync(0xffffffffu, w1, src);
            float sw2 = __shfl_sync(0xffffffffu, w2, src);

            uint2 h0 = __ldg(&g_vnh[sj0 * B_N + b]);
            uint2 h1 = __ldg(&g_vnh[sj1 * B_N + b]);
            uint2 h2 = __ldg(&g_vnh[sj2 * B_N + b]);

            float2 n0xy = __half22float2(*reinterpret_cast<__half2*>(&h0.x));
            float  n0z  = __low2float(*reinterpret_cast<__half2*>(&h0.y));
            float2 n1xy = __half22float2(*reinterpret_cast<__half2*>(&h1.x));
            float  n1z  = __low2float(*reinterpret_cast<__half2*>(&h1.y));
            float2 n2xy = __half22float2(*reinterpret_cast<__half2*>(&h2.x));
            float  n2z  = __low2float(*reinterpret_cast<__half2*>(&h2.y));

            accx += sw0 * n0xy.x + sw1 * n1xy.x + sw2 * n2xy.x;
            accy += sw0 * n0xy.y + sw1 * n1xy.y + sw2 * n2xy.y;
            accz += sw0 * n0z    + sw1 * n1z    + sw2 * n2z;
        }

        float sc = 1.f / (float)K_N;
        int vloc = local >> 3;
        sout[b * 96 + vloc * 3 + 0] = accx * sc;
        sout[b * 96 + vloc * 3 + 1] = accy * sc;
        sout[b * 96 + vloc * 3 + 2] = accz * sc;
    }
    __syncthreads();

    // Coalesced write-out: out[b][v][c], 768 floats per block.
    int v0 = blockIdx.x * 32;
    for (int i = local; i < 32 * B_N * 3; i += 256) {
        int bb = i / 96;
        int r  = i - bb * 96;
        int vv = v0 + r / 3;
        if (vv < V_N) out[(size_t)bb * (V_N * 3) + (size_t)v0 * 3 + r] = sout[i];
    }
}

extern "C" void kernel_launch(void* const* d_in, const int* in_sizes, int n_in,
                              void* d_out, int out_size)
{
    const float* verts  = (const float*)d_in[0];  // [B, V, 3]
    const float* bary   = (const float*)d_in[1];  // [U, U, 3]
    const float* vt     = (const float*)d_in[2];  // [T, 2]
    const int*   vi     = (const int*)  d_in[3];  // [Fc, 3]
    const int*   idximg = (const int*)  d_in[4];  // [U, U, 3]
    const int*   v2uv   = (const int*)  d_in[5];  // [V, K]
    float*       out    = (float*)d_out;          // [B, V, 3]

    (void)in_sizes; (void)n_in; (void)out_size;

    prep_kernel<<<(V_N * B_N + 255) / 256, 256>>>(verts);
    face_pass_kernel<<<(FC_N * 2 + 255) / 256, 256>>>(vi);
    norm_vn_kernel<<<(V_N * B_N + 255) / 256, 256>>>();
    sample_pass_kernel<<<(V_N + 31) / 32, 256>>>(bary, vt, idximg, v2uv, out);
}

// round 10
// speedup vs baseline: 1.0442x; 1.0442x over previous
#include <cuda_runtime.h>
#include <cuda_fp16.h>

#define V_N  100000
#define B_N  8
#define FC_N 200000
#define U_N  1024
#define T_N  110000
#define K_N  2
#define EPS_F 1e-5f

// Scratch:
__device__ float2 g_vxy[V_N * B_N];  // transposed verts xy [v][b], 6.4 MB
__device__ float  g_vz [V_N * B_N];  // transposed verts z  [v][b], 3.2 MB
__device__ float4 g_vn [V_N * B_N];  // accumulated vertex normals [v][b], 12.8 MB
__device__ uint2  g_vnh[V_N * B_N];  // normalized vn as half4 [v][b], 6.4 MB

__device__ __forceinline__ void red_add_v4(float4* ptr, float x, float y, float z) {
    asm volatile("red.global.add.v4.f32 [%0], {%1, %2, %3, %4};"
                 :: "l"(ptr), "f"(x), "f"(y), "f"(z), "f"(0.0f)
                 : "memory");
}

// Transpose verts -> split xy/z arrays AND zero g_vn. b fastest => coalesced.
__global__ __launch_bounds__(256) void prep_kernel(const float* __restrict__ verts) {
    int i = blockIdx.x * blockDim.x + threadIdx.x;
    if (i >= V_N * B_N) return;
    int v = i >> 3;
    int b = i & 7;
    const float* p = verts + (size_t)b * (V_N * 3) + v * 3;
    float x = __ldg(p), y = __ldg(p + 1), z = __ldg(p + 2);
    g_vxy[i] = make_float2(x, y);
    g_vz[i]  = z;
    g_vn[i]  = make_float4(0.f, 0.f, 0.f, 0.f);
}

// One thread per (face, batch); b fastest. 96B/8-lane coalesced vertex loads,
// 3 vector reductions per thread.  (R8 form — protected.)
__global__ __launch_bounds__(256) void face_pass_kernel(const int* __restrict__ vi)
{
    int tid = blockIdx.x * blockDim.x + threadIdx.x;
    if (tid >= FC_N * B_N) return;
    int f = tid >> 3;
    int b = tid & 7;

    int i0 = __ldg(&vi[f * 3 + 0]);
    int i1 = __ldg(&vi[f * 3 + 1]);
    int i2 = __ldg(&vi[f * 3 + 2]);

    float2 Axy = __ldg(&g_vxy[i0 * B_N + b]);
    float2 Bxy = __ldg(&g_vxy[i1 * B_N + b]);
    float2 Cxy = __ldg(&g_vxy[i2 * B_N + b]);
    float  Az  = __ldg(&g_vz [i0 * B_N + b]);
    float  Bz  = __ldg(&g_vz [i1 * B_N + b]);
    float  Cz  = __ldg(&g_vz [i2 * B_N + b]);

    float e1x = Bxy.x - Axy.x, e1y = Bxy.y - Axy.y, e1z = Bz - Az;
    float e2x = Cxy.x - Axy.x, e2y = Cxy.y - Axy.y, e2z = Cz - Az;
    float nx = e1y * e2z - e1z * e2y;
    float ny = e1z * e2x - e1x * e2z;
    float nz = e1x * e2y - e1y * e2x;

    float nrm = sqrtf(nx * nx + ny * ny + nz * nz);
    if (nrm >= EPS_F) {
        float inv = 1.f / nrm;
        nx *= inv; ny *= inv; nz *= inv;
    }

    red_add_v4(&g_vn[i0 * B_N + b], nx, ny, nz);
    red_add_v4(&g_vn[i1 * B_N + b], nx, ny, nz);
    red_add_v4(&g_vn[i2 * B_N + b], nx, ny, nz);
}

// Normalize in fp32, emit half4.
__global__ __launch_bounds__(256) void norm_vn_kernel() {
    int i = blockIdx.x * blockDim.x + threadIdx.x;
    if (i >= V_N * B_N) return;
    float4 v = g_vn[i];
    float nrm = sqrtf(v.x * v.x + v.y * v.y + v.z * v.z);
    if (nrm >= EPS_F) {
        float inv = 1.f / nrm;
        v.x *= inv; v.y *= inv; v.z *= inv;
    }
    __half2 xy = __floats2half2_rn(v.x, v.y);
    __half2 z0 = __floats2half2_rn(v.z, 0.f);
    uint2 u;
    *reinterpret_cast<__half2*>(&u.x) = xy;
    *reinterpret_cast<__half2*>(&u.y) = z0;
    g_vnh[i] = u;
}

// Two-stage sample pass, block = 32 vertices, 256 threads.
// Stage 1: thread (vloc,k,tap) computes its tap record; each (j,w) pair is
//          PACKED into one u32: j (17b) | wq (15b, unorm15).
// Stage 2: (vloc,b); fetch records via 3 shuffles per tap (was 6).
__global__ __launch_bounds__(256) void sample_pass_kernel(
    const float* __restrict__ bary,
    const float* __restrict__ vt,
    const int*   __restrict__ idximg,
    const int*   __restrict__ v2uv,
    float*       __restrict__ out)
{
    __shared__ float sout[32 * B_N * 3];

    int local = threadIdx.x;
    int lane  = local & 31;

    // ---- stage 1: packed tap record in registers ----
    unsigned p0 = 0, p1 = 0, p2 = 0;
    {
        int vloc = local >> 3;
        int k    = (local >> 2) & 1;
        int tap  = local & 3;
        int v    = blockIdx.x * 32 + vloc;

        if (v < V_N) {
            int t = __ldg(&v2uv[v * K_N + k]);
            float2 uv = __ldg(reinterpret_cast<const float2*>(vt) + t);

            // ix = ((2u-1 + 1)*W - 1)*0.5 = u*W - 0.5
            float ix = uv.x * (float)U_N - 0.5f;
            float iy = uv.y * (float)U_N - 0.5f;
            float x0f = floorf(ix), y0f = floorf(iy);
            int x0 = (int)x0f, y0 = (int)y0f;
            float wx1 = ix - x0f, wx0 = 1.f - wx1;
            float wy1 = iy - y0f, wy0 = 1.f - wy1;

            int xi = x0 + (tap & 1);
            int yi = y0 + (tap >> 1);
            bool inb = (xi >= 0) & (xi < U_N) & (yi >= 0) & (yi < U_N);
            int xc = min(max(xi, 0), U_N - 1);
            int yc = min(max(yi, 0), U_N - 1);
            int pix = yc * U_N + xc;

            int a0 = __ldg(&idximg[pix * 3 + 0]);
            int a1 = __ldg(&idximg[pix * 3 + 1]);
            int a2 = __ldg(&idximg[pix * 3 + 2]);
            bool valid = inb & (a0 != -1) & (a1 != -1) & (a2 != -1);

            float wt = ((tap & 1) ? wx1 : wx0) * ((tap >> 1) ? wy1 : wy0);
            wt = valid ? wt : 0.f;

            float b0 = __ldg(&bary[pix * 3 + 0]);
            float b1 = __ldg(&bary[pix * 3 + 1]);
            float b2 = __ldg(&bary[pix * 3 + 2]);

            unsigned j0 = (unsigned)min(max(a0, 0), V_N - 1);
            unsigned j1 = (unsigned)min(max(a1, 0), V_N - 1);
            unsigned j2 = (unsigned)min(max(a2, 0), V_N - 1);
            // w in [0,1] -> unorm15
            unsigned q0 = (unsigned)__float2int_rn(__saturatef(wt * b0) * 32767.f);
            unsigned q1 = (unsigned)__float2int_rn(__saturatef(wt * b1) * 32767.f);
            unsigned q2 = (unsigned)__float2int_rn(__saturatef(wt * b2) * 32767.f);

            p0 = j0 | (q0 << 17);
            p1 = j1 | (q1 << 17);
            p2 = j2 | (q2 << 17);
        }
    }

    // ---- stage 2: (vloc, b); 3 shuffles per tap ----
    {
        int b       = local & 7;
        int srcbase = lane & 24;   // first lane of this 8-lane subgroup
        const float qs = 1.f / 32767.f;

        float accx = 0.f, accy = 0.f, accz = 0.f;

        #pragma unroll
        for (int e = 0; e < 8; e++) {
            int src = srcbase + e;
            unsigned r0 = __shfl_sync(0xffffffffu, p0, src);
            unsigned r1 = __shfl_sync(0xffffffffu, p1, src);
            unsigned r2 = __shfl_sync(0xffffffffu, p2, src);

            int sj0 = (int)(r0 & 0x1FFFFu);
            int sj1 = (int)(r1 & 0x1FFFFu);
            int sj2 = (int)(r2 & 0x1FFFFu);
            float sw0 = (float)(r0 >> 17) * qs;
            float sw1 = (float)(r1 >> 17) * qs;
            float sw2 = (float)(r2 >> 17) * qs;

            uint2 h0 = __ldg(&g_vnh[sj0 * B_N + b]);
            uint2 h1 = __ldg(&g_vnh[sj1 * B_N + b]);
            uint2 h2 = __ldg(&g_vnh[sj2 * B_N + b]);

            float2 n0xy = __half22float2(*reinterpret_cast<__half2*>(&h0.x));
            float  n0z  = __low2float(*reinterpret_cast<__half2*>(&h0.y));
            float2 n1xy = __half22float2(*reinterpret_cast<__half2*>(&h1.x));
            float  n1z  = __low2float(*reinterpret_cast<__half2*>(&h1.y));
            float2 n2xy = __half22float2(*reinterpret_cast<__half2*>(&h2.x));
            float  n2z  = __low2float(*reinterpret_cast<__half2*>(&h2.y));

            accx += sw0 * n0xy.x + sw1 * n1xy.x + sw2 * n2xy.x;
            accy += sw0 * n0xy.y + sw1 * n1xy.y + sw2 * n2xy.y;
            accz += sw0 * n0z    + sw1 * n1z    + sw2 * n2z;
        }

        float sc = 1.f / (float)K_N;
        int vloc = local >> 3;
        sout[b * 96 + vloc * 3 + 0] = accx * sc;
        sout[b * 96 + vloc * 3 + 1] = accy * sc;
        sout[b * 96 + vloc * 3 + 2] = accz * sc;
    }
    __syncthreads();

    // Coalesced write-out: out[b][v][c], 768 floats per block.
    int v0 = blockIdx.x * 32;
    for (int i = local; i < 32 * B_N * 3; i += 256) {
        int bb = i / 96;
        int r  = i - bb * 96;
        int vv = v0 + r / 3;
        if (vv < V_N) out[(size_t)bb * (V_N * 3) + (size_t)v0 * 3 + r] = sout[i];
    }
}

extern "C" void kernel_launch(void* const* d_in, const int* in_sizes, int n_in,
                              void* d_out, int out_size)
{
    const float* verts  = (const float*)d_in[0];  // [B, V, 3]
    const float* bary   = (const float*)d_in[1];  // [U, U, 3]
    const float* vt     = (const float*)d_in[2];  // [T, 2]
    const int*   vi     = (const int*)  d_in[3];  // [Fc, 3]
    const int*   idximg = (const int*)  d_in[4];  // [U, U, 3]
    const int*   v2uv   = (const int*)  d_in[5];  // [V, K]
    float*       out    = (float*)d_out;          // [B, V, 3]

    (void)in_sizes; (void)n_in; (void)out_size;

    prep_kernel<<<(V_N * B_N + 255) / 256, 256>>>(verts);
    face_pass_kernel<<<(FC_N * B_N + 255) / 256, 256>>>(vi);
    norm_vn_kernel<<<(V_N * B_N + 255) / 256, 256>>>();
    sample_pass_kernel<<<(V_N + 31) / 32, 256>>>(bary, vt, idximg, v2uv, out);
}